// round 4
// baseline (speedup 1.0000x reference)
#include <cuda_runtime.h>
#include <cuda_bf16.h>
#include <math.h>

#define BB 16
#define NN 25200
#define NCLS 80
#define KPRE 1024
#define MAXDET 300
#define OUTC 89

// ---------------- scratch (device globals; zero-initialized at load) ----------------
__device__ int                g_cls[BB*NN];
__device__ unsigned           g_cnt[BB];                 // zeroed at end of k_sortsel
__device__ unsigned long long g_cand[BB*NN];
__device__ unsigned long long g_top[BB*KPRE];
__device__ float4             g_boxes[BB*KPRE];
__device__ unsigned           g_validw[BB*32];
__device__ unsigned           g_mask[BB*KPRE*32];

static __device__ __forceinline__ int score_bin(unsigned bits) {
    int bin = (int)(bits >> 16) - 0x3E00;
    return bin < 0 ? 0 : (bin > 511 ? 511 : bin);
}

// ---------------- phase 1: per-anchor score/argmax, obj-gated, compacted push ----------------
__global__ void k_score(const float* __restrict__ pred) {
    __shared__ unsigned long long sbuf[8];
    __shared__ unsigned scnt;
    __shared__ unsigned sbase;
    if (threadIdx.x == 0) scnt = 0;
    __syncthreads();

    int warp = (blockIdx.x * blockDim.x + threadIdx.x) >> 5;   // global anchor id
    int lane = threadIdx.x & 31;
    size_t base = (size_t)warp * 85;
    float l0 = pred[base + lane];
    float obj = __shfl_sync(0xffffffffu, l0, 4);
    int b = warp / NN;

    if (obj > 0.4f) {   // warp-uniform: xc gate; skips 2/3 of the row read when false
        float l1 = pred[base + 32 + lane];
        float l2 = (lane < 21) ? pred[base + 64 + lane] : 0.f;

        float bv = -1.f; int bi = 0x7fffffff;
        if (lane >= 5) { float p = l0 * obj; int c = lane - 5;  if (p > bv) { bv = p; bi = c; } }
        { float p = l1 * obj; int c = 27 + lane; if (p > bv || (p == bv && c < bi)) { bv = p; bi = c; } }
        if (lane < 21) { float p = l2 * obj; int c = 59 + lane; if (p > bv || (p == bv && c < bi)) { bv = p; bi = c; } }

        #pragma unroll
        for (int off = 16; off; off >>= 1) {
            float ov = __shfl_xor_sync(0xffffffffu, bv, off);
            int   oi = __shfl_xor_sync(0xffffffffu, bi, off);
            if (ov > bv || (ov == bv && oi < bi)) { bv = ov; bi = oi; }
        }
        if (lane == 0) {
            float conf = bv;
            if (conf > 0.4f) {
                unsigned bits = __float_as_uint(conf);
                g_cls[warp] = bi;
                unsigned ai = (unsigned)(warp - b*NN);
                unsigned long long key =
                    ((unsigned long long)bits << 32) | (0xFFFFFFFFu - ai);
                unsigned p = atomicAdd(&scnt, 1u);
                sbuf[p] = key;
            }
        }
    }
    __syncthreads();
    if (threadIdx.x == 0 && scnt) sbase = atomicAdd(&g_cnt[b], scnt);
    __syncthreads();
    if (threadIdx.x < scnt)
        g_cand[(size_t)b*NN + sbase + threadIdx.x] = sbuf[threadIdx.x];
}

// ---------------- phase 2: hist + exact threshold + small sort(T-bin) + 1024 sort ----------------
__global__ void k_sortsel(const float* __restrict__ pred) {
    __shared__ unsigned long long skA[1024];
    __shared__ unsigned long long tbuf[4096];
    __shared__ unsigned hist[512];
    __shared__ int sT;
    __shared__ unsigned nA, nB;
    int b = blockIdx.x, tid = threadIdx.x;   // 1024 threads

    skA[tid] = 0ull;
    for (int i = tid; i < 4096; i += 1024) tbuf[i] = 0ull;
    if (tid < 512) hist[tid] = 0u;
    if (tid == 0) { nA = 0; nB = 0; }
    __syncthreads();

    unsigned nc = min(g_cnt[b], (unsigned)NN);
    const unsigned long long* cand = &g_cand[(size_t)b*NN];
    for (unsigned i = tid; i < nc; i += 1024) {
        unsigned bits = (unsigned)(cand[i] >> 32);
        atomicAdd(&hist[score_bin(bits)], 1u);
    }
    __syncthreads();
    // suffix sum over 512 bins
    for (int off = 1; off < 512; off <<= 1) {
        unsigned v = 0;
        if (tid < 512 && tid + off < 512) v = hist[tid + off];
        __syncthreads();
        if (tid < 512) hist[tid] += v;
        __syncthreads();
    }
    if (tid < 512) {
        unsigned suf  = hist[tid];
        unsigned sufn = (tid < 511) ? hist[tid + 1] : 0u;
        if (tid == 0 && suf < (unsigned)KPRE) sT = -1;
        if (suf >= (unsigned)KPRE && sufn < (unsigned)KPRE) sT = tid;
    }
    __syncthreads();
    int T = sT;
    // scatter: bin>T -> A (unsorted, guaranteed < 1024); bin==T -> tbuf
    for (unsigned i = tid; i < nc; i += 1024) {
        unsigned long long key = cand[i];
        int bin = score_bin((unsigned)(key >> 32));
        if (bin > T) {
            unsigned p = atomicAdd(&nA, 1u);
            if (p < 1024u) skA[p] = key;
        } else if (bin == T) {
            unsigned p = atomicAdd(&nB, 1u);
            if (p < 4096u) tbuf[p] = key;
        }
    }
    __syncthreads();
    unsigned m = min(nB, 4096u);
    if (m > 0u) {
        unsigned St = 32; while (St < m) St <<= 1;
        // bitonic sort tbuf[0..St) descending
        for (unsigned k2 = 2; k2 <= St; k2 <<= 1) {
            for (unsigned j = k2 >> 1; j > 0; j >>= 1) {
                for (unsigned i = tid; i < St; i += 1024) {
                    unsigned ixj = i ^ j;
                    if (ixj > i) {
                        bool up = ((i & k2) == 0);
                        unsigned long long x = tbuf[i], y = tbuf[ixj];
                        bool sw = up ? (x < y) : (x > y);
                        if (sw) { tbuf[i] = y; tbuf[ixj] = x; }
                    }
                }
                __syncthreads();
            }
        }
        // append top (1024 - nA) of sorted T-bin items
        unsigned a = nA;                 // < 1024
        unsigned needK = 1024u - a;
        if (tid < needK) skA[a + tid] = tbuf[tid];
        __syncthreads();
    }
    // final bitonic sort of exactly 1024 keys, descending (zeros sink)
    for (unsigned k2 = 2; k2 <= 1024; k2 <<= 1) {
        for (unsigned j = k2 >> 1; j > 0; j >>= 1) {
            unsigned i = tid, ixj = i ^ j;
            if (ixj > i) {
                bool up = ((i & k2) == 0);
                unsigned long long x = skA[i], y = skA[ixj];
                bool sw = up ? (x < y) : (x > y);
                if (sw) { skA[i] = y; skA[ixj] = x; }
            }
            __syncthreads();
        }
    }
    // emit top-1024
    {
        unsigned long long key = skA[tid];
        unsigned bits = (unsigned)(key >> 32);
        unsigned anchor = bits ? (0xFFFFFFFFu - (unsigned)key) : 0u;
        g_top[b*KPRE + tid] = ((unsigned long long)bits << 32) | anchor;
        float4 bx = make_float4(0.f, 0.f, 0.f, 0.f);
        if (bits) {
            size_t pb = ((size_t)b*NN + anchor) * 85;
            float x = pred[pb], y = pred[pb+1], w = pred[pb+2], h = pred[pb+3];
            float off = (float)g_cls[b*NN + anchor] * 4096.0f;
            bx.x = (x - w*0.5f) + off;
            bx.y = (y - h*0.5f) + off;
            bx.z = (x + w*0.5f) + off;
            bx.w = (y + h*0.5f) + off;
        }
        g_boxes[b*KPRE + tid] = bx;
        unsigned bal = __ballot_sync(0xffffffffu, bits != 0u);
        if ((tid & 31) == 0) g_validw[b*32 + (tid >> 5)] = bal;
    }
    __syncthreads();
    if (tid == 0) g_cnt[b] = 0;   // reset for next replay
}

// ---------------- phase 3: IoU suppression bit-mask (upper triangle only) ----------------
__global__ void k_iou() {
    __shared__ float4 sb[1024];
    __shared__ float  sa[1024];
    __shared__ unsigned tileS[32][33];
    int b = blockIdx.y, tile = blockIdx.x;
    int tid = threadIdx.x;
    float4 v = g_boxes[b*KPRE + tid];
    sb[tid] = v;
    sa[tid] = (v.z - v.x) * (v.w - v.y);
    __syncthreads();

    int w = tid >> 5, rl = tid & 31;
    int r = tile*32 + rl;
    unsigned bits = 0u;
    if (w >= tile) {   // words below the diagonal are all-zero (j>i only)
        float4 rb_ = sb[r];
        float  ra  = sa[r];
        int j0 = w * 32;
        #pragma unroll 4
        for (int t = 0; t < 32; t++) {
            int j = j0 + t;
            float4 cb = sb[j];
            float ltx = fmaxf(rb_.x, cb.x), lty = fmaxf(rb_.y, cb.y);
            float rbx = fminf(rb_.z, cb.z), rby = fminf(rb_.w, cb.w);
            float iw = fmaxf(rbx - ltx, 0.f), ih = fmaxf(rby - lty, 0.f);
            float inter = iw * ih;
            float den = ((ra + sa[j]) - inter) + 1e-7f;
            float thr = 0.45f * den;
            bool sup;
            if (inter > thr * (1.0f + 1e-5f))       sup = true;
            else if (inter < thr * (1.0f - 1e-5f))  sup = false;
            else                                    sup = (__fdiv_rn(inter, den) > 0.45f);
            sup = sup && (j > r);
            bits |= sup ? (1u << t) : 0u;
        }
    }
    tileS[rl][w] = bits;
    __syncthreads();
    int rl2 = tid >> 5, w2 = tid & 31;
    g_mask[((size_t)b*KPRE + tile*32 + rl2) * 32 + w2] = tileS[rl2][w2];
}

// ---------------- phase 4: greedy scan (SMEM) + output emission, fused ----------------
__global__ void k_finish(const float* __restrict__ pred,
                         const float* __restrict__ conf_logits,
                         const float* __restrict__ logits,
                         const float* __restrict__ head,
                         float* __restrict__ out) {
    extern __shared__ unsigned sm[];            // 1024*32 words = 128 KB
    __shared__ int s_sel[MAXDET];
    __shared__ int s_nk;
    int b = blockIdx.x, tid = threadIdx.x;      // 1024 threads
    const uint4* mp4 = (const uint4*)&g_mask[(size_t)b*KPRE*32];
    uint4* sm4 = (uint4*)sm;
    #pragma unroll
    for (int it = 0; it < 8; it++)
        sm4[it*1024 + tid] = mp4[it*1024 + tid];
    __syncthreads();

    if (tid < 32) {
        int lane = tid;
        unsigned alive = g_validw[b*32 + lane];   // lane holds indices [lane*32, lane*32+32)
        int cnt = 0;
        while (cnt < MAXDET) {
            unsigned bal = __ballot_sync(0xffffffffu, alive != 0u);
            if (!bal) break;
            int w = __ffs(bal) - 1;
            unsigned aw = __shfl_sync(0xffffffffu, alive, w);
            int i = w*32 + (__ffs(aw) - 1);
            unsigned row = sm[i*32 + lane];
            alive &= ~row;
            if (lane == w) alive &= ~(1u << (i & 31));
            if (lane == 0) s_sel[cnt] = i;
            cnt++;
        }
        if (lane == 0) s_nk = cnt;
    }
    __syncthreads();

    int nk = s_nk;
    int wid = tid >> 5, lane = tid & 31;
    for (int r = wid; r < MAXDET; r += 32) {
        size_t obase = ((size_t)b*MAXDET + r) * OUTC;
        if (r < nk) {
            int slot = s_sel[r];
            unsigned long long key = g_top[b*KPRE + slot];
            float score = __uint_as_float((unsigned)(key >> 32));
            unsigned anchor = (unsigned)key;
            size_t a = (size_t)b*NN + anchor;
            float objsig = 1.f / (1.f + expf(-conf_logits[a*5 + 4]));
            for (int c = lane; c < OUTC; c += 32) {
                float val;
                if (c < 4) {
                    float x = pred[a*85], y = pred[a*85+1], w = pred[a*85+2], h = pred[a*85+3];
                    val = (c == 0) ? x - w*0.5f : (c == 1) ? y - h*0.5f
                        : (c == 2) ? x + w*0.5f : y + h*0.5f;
                } else if (c == 4)  val = score;
                else if (c == 5)    val = (float)g_cls[a];
                else if (c < 86)    val = (1.f / (1.f + expf(-logits[a*80 + (c - 6)]))) * objsig;
                else if (c == 86)   val = objsig;
                else if (c == 87)   val = head[a];
                else                val = 1.f;
                out[obase + c] = val;
            }
        } else {
            for (int c = lane; c < OUTC; c += 32) out[obase + c] = 0.f;
        }
    }
}

extern "C" void kernel_launch(void* const* d_in, const int* in_sizes, int n_in,
                              void* d_out, int out_size) {
    const float* pred = (const float*)d_in[0];
    const float* cl   = (const float*)d_in[1];
    const float* lg   = (const float*)d_in[2];
    const float* hd   = (const float*)d_in[3];
    float* out = (float*)d_out;

    cudaFuncSetAttribute(k_finish, cudaFuncAttributeMaxDynamicSharedMemorySize,
                         KPRE * 32 * (int)sizeof(unsigned));

    {
        // one warp per anchor, 8 anchors per 256-thread block; 25200 % 8 == 0
        int blocks = (BB*NN) / 8;
        k_score<<<blocks, 256>>>(pred);
    }
    k_sortsel<<<BB, 1024>>>(pred);
    k_iou<<<dim3(32, BB), 1024>>>();
    k_finish<<<BB, 1024, KPRE * 32 * sizeof(unsigned)>>>(pred, cl, lg, hd, out);
}